// round 1
// baseline (speedup 1.0000x reference)
#include <cuda_runtime.h>
#include <cstddef>

// ---------------------------------------------------------------------------
// MusicTransformer: B=2, L=1024, D=256, H=4, dh=64, NUM_LAYER=6, V=240
// Full fp32 implementation.
//
// Key identity (derived from the reference's pad/reshape skew + mask):
//   Srel[i,j] = (j <= i) ? dot(q_i, E[L-1-i+j]) : 0
// so Srel is a gather from QE2 = Q @ E^T.
// ---------------------------------------------------------------------------

#define L_CONST 1024
#define D_CONST 256

// ---- scratch layout (floats) ----
#define XSZ      (2*1024*256)          // 524288
#define OFF_X0   0
#define OFF_X1   (OFF_X0 + XSZ)
#define OFF_X2   (OFF_X1 + XSZ)
#define OFF_Q    (OFF_X2 + XSZ)
#define OFF_K    (OFF_Q + XSZ)
#define OFF_V    (OFF_K + XSZ)
#define OFF_ATT  (OFF_V + XSZ)
#define OFF_S    (OFF_ATT + XSZ)                 // 8*1024*1024 scores / probs
#define OFF_QE   (OFF_S + 8*1024*1024)           // 8*1024*1024 Q@E^T
#define OFF_PART (OFF_QE + 8*1024*1024)          // 2*256*240 fc partials
#define SCRATCH_TOTAL (OFF_PART + 2*256*240)

__device__ float g_scratch[SCRATCH_TOTAL];

// ---------------------------------------------------------------------------
// Embedding: x[b,l,d] = emb_table[tokens[b,l], d] + pos_emb[l, d]
// ---------------------------------------------------------------------------
__global__ __launch_bounds__(256) void k_embed(const int* __restrict__ tokens,
                                               const float* __restrict__ emb,
                                               const float* __restrict__ pos,
                                               float* __restrict__ x) {
    int idx = blockIdx.x * 256 + threadIdx.x;          // < 524288
    int tok = tokens[idx >> 8];
    int d   = idx & 255;
    int pd  = idx & (262144 - 1);                      // (l*256 + d)
    x[idx] = emb[tok * 256 + d] + pos[pd];
}

// ---------------------------------------------------------------------------
// Generic GEMM: out = act(A[2048x256] @ W[256x256] + bias) (+ residual)
// flags: 1 = split-head output layout [B,H,L,dh]
//        2 = add residual res[r*256+c]
//        4 = leaky relu (0.2)
// grid (4, 32), block 256
// ---------------------------------------------------------------------------
__global__ __launch_bounds__(256) void k_gemm256(const float* __restrict__ A,
                                                 const float* __restrict__ W,
                                                 const float* __restrict__ bias,
                                                 const float* __restrict__ res,
                                                 float* __restrict__ out,
                                                 int flags) {
    __shared__ __align__(16) float As[64][68];
    __shared__ __align__(16) float Ws[64][68];
    int t  = threadIdx.x;
    int tx = t & 15, ty = t >> 4;
    int m0 = blockIdx.y * 64, n0 = blockIdx.x * 64;
    float acc[4][4] = {};

    for (int k0 = 0; k0 < 256; k0 += 64) {
        #pragma unroll
        for (int ff = 0; ff < 4; ff++) {
            int f   = t + ff * 256;
            int row = f >> 4;
            int c4  = (f & 15) << 2;
            *(float4*)&As[row][c4] = *(const float4*)&A[(m0 + row) * 256 + k0 + c4];
            *(float4*)&Ws[row][c4] = *(const float4*)&W[(k0 + row) * 256 + n0 + c4];
        }
        __syncthreads();
        #pragma unroll 16
        for (int kk = 0; kk < 64; kk++) {
            float4 w4 = *(float4*)&Ws[kk][tx * 4];
            #pragma unroll
            for (int a = 0; a < 4; a++) {
                float av = As[ty * 4 + a][kk];
                acc[a][0] += av * w4.x;
                acc[a][1] += av * w4.y;
                acc[a][2] += av * w4.z;
                acc[a][3] += av * w4.w;
            }
        }
        __syncthreads();
    }

    #pragma unroll
    for (int a = 0; a < 4; a++) {
        int r = m0 + ty * 4 + a;
        #pragma unroll
        for (int bb = 0; bb < 4; bb++) {
            int c = n0 + tx * 4 + bb;
            float v = acc[a][bb] + bias[c];
            if (flags & 4) v = v > 0.f ? v : 0.2f * v;
            if (flags & 2) v += res[r * 256 + c];
            if (flags & 1) {
                // [B,H,L,dh]: ((b*4+h)*1024 + l)*64 + d
                int b = r >> 10, l = r & 1023, h = c >> 6, d = c & 63;
                out[(((b << 2) + h) << 16) + (l << 6) + d] = v;
            } else {
                out[r * 256 + c] = v;
            }
        }
    }
}

// ---------------------------------------------------------------------------
// Scores: per z in [0,8): Out[z][i][j] = dot(Q[z][i], Bmat[(z)][j])  (K = 64)
// batched=1 -> Bmat is per-z (K matrix); batched=0 -> shared (E matrix)
// grid (16, 16, 8), block 256
// ---------------------------------------------------------------------------
__global__ __launch_bounds__(256) void k_scores(const float* __restrict__ Q,
                                                const float* __restrict__ Bm,
                                                float* __restrict__ out,
                                                int batched) {
    __shared__ __align__(16) float Qs[64][68];
    __shared__ __align__(16) float Bs[64][68];
    int z = blockIdx.z;
    const float* Qz = Q + z * 65536;
    const float* Bz = batched ? (Bm + z * 65536) : Bm;
    float* Oz = out + (size_t)z * 1048576;
    int t = threadIdx.x, tx = t & 15, ty = t >> 4;
    int i0 = blockIdx.y * 64, j0 = blockIdx.x * 64;

    #pragma unroll
    for (int ff = 0; ff < 4; ff++) {
        int f   = t + ff * 256;
        int row = f >> 4;
        int c4  = (f & 15) << 2;
        *(float4*)&Qs[row][c4] = *(const float4*)&Qz[(i0 + row) * 64 + c4];
        *(float4*)&Bs[row][c4] = *(const float4*)&Bz[(j0 + row) * 64 + c4];
    }
    __syncthreads();

    float acc[4][4] = {};
    #pragma unroll
    for (int d4 = 0; d4 < 16; d4++) {
        float4 q4[4], b4[4];
        #pragma unroll
        for (int a = 0; a < 4; a++) q4[a] = *(float4*)&Qs[ty * 4 + a][d4 * 4];
        #pragma unroll
        for (int b = 0; b < 4; b++) b4[b] = *(float4*)&Bs[tx * 4 + b][d4 * 4];
        #pragma unroll
        for (int a = 0; a < 4; a++)
            #pragma unroll
            for (int b = 0; b < 4; b++) {
                acc[a][b] += q4[a].x * b4[b].x;
                acc[a][b] += q4[a].y * b4[b].y;
                acc[a][b] += q4[a].z * b4[b].z;
                acc[a][b] += q4[a].w * b4[b].w;
            }
    }
    #pragma unroll
    for (int a = 0; a < 4; a++)
        #pragma unroll
        for (int b = 0; b < 4; b++)
            Oz[(size_t)(i0 + ty * 4 + a) * 1024 + j0 + tx * 4 + b] = acc[a][b];
}

// ---------------------------------------------------------------------------
// Softmax with fused relative-position skew (in place on S):
//   logit[j] = (S[i,j] + (j<=i ? QE[i, 1023-i+j] : 0)) / 8 ; P = softmax_j
// grid (1024, 8), block 256
// ---------------------------------------------------------------------------
__global__ __launch_bounds__(256) void k_softmax(float* __restrict__ S,
                                                 const float* __restrict__ QE) {
    int i = blockIdx.x, z = blockIdx.y, t = threadIdx.x;
    float* Srow = S + (size_t)z * 1048576 + (size_t)i * 1024;
    const float* Erow = QE + (size_t)z * 1048576 + (size_t)i * 1024;

    float vals[4];
    float mx = -1e30f;
    #pragma unroll
    for (int r = 0; r < 4; r++) {
        int j = r * 256 + t;
        float v = Srow[j];
        if (j <= i) v += Erow[1023 - i + j];
        v *= 0.125f;
        vals[r] = v;
        mx = fmaxf(mx, v);
    }

    __shared__ float redm[8];
    __shared__ float reds[8];
    int lane = t & 31, warp = t >> 5;
    #pragma unroll
    for (int o = 16; o; o >>= 1) mx = fmaxf(mx, __shfl_xor_sync(0xffffffffu, mx, o));
    if (lane == 0) redm[warp] = mx;
    __syncthreads();
    if (t == 0) {
        float m = redm[0];
        #pragma unroll
        for (int w = 1; w < 8; w++) m = fmaxf(m, redm[w]);
        redm[0] = m;
    }
    __syncthreads();
    mx = redm[0];

    float s = 0.f;
    #pragma unroll
    for (int r = 0; r < 4; r++) {
        vals[r] = expf(vals[r] - mx);
        s += vals[r];
    }
    #pragma unroll
    for (int o = 16; o; o >>= 1) s += __shfl_xor_sync(0xffffffffu, s, o);
    if (lane == 0) reds[warp] = s;
    __syncthreads();
    if (t == 0) {
        float tt = reds[0];
        #pragma unroll
        for (int w = 1; w < 8; w++) tt += reds[w];
        reds[0] = tt;
    }
    __syncthreads();
    float inv = 1.f / reds[0];
    #pragma unroll
    for (int r = 0; r < 4; r++) Srow[r * 256 + t] = vals[r] * inv;
}

// ---------------------------------------------------------------------------
// AV: out[b, l, h*64+d] = sum_j P[z][l][j] * V[z][j][d]   (z = b*4+h)
// grid (16, 8), block 256
// ---------------------------------------------------------------------------
__global__ __launch_bounds__(256) void k_av(const float* __restrict__ P,
                                            const float* __restrict__ Vm,
                                            float* __restrict__ out) {
    __shared__ __align__(16) float Ps[64][68];
    __shared__ __align__(16) float Vs[64][68];
    int z = blockIdx.y;
    const float* Pz = P + (size_t)z * 1048576;
    const float* Vz = Vm + z * 65536;
    int t = threadIdx.x, tx = t & 15, ty = t >> 4;
    int l0 = blockIdx.x * 64;
    float acc[4][4] = {};

    for (int kt = 0; kt < 16; kt++) {
        #pragma unroll
        for (int ff = 0; ff < 4; ff++) {
            int f   = t + ff * 256;
            int row = f >> 4;
            int c4  = (f & 15) << 2;
            *(float4*)&Ps[row][c4] = *(const float4*)&Pz[(size_t)(l0 + row) * 1024 + kt * 64 + c4];
            *(float4*)&Vs[row][c4] = *(const float4*)&Vz[(kt * 64 + row) * 64 + c4];
        }
        __syncthreads();
        #pragma unroll 16
        for (int jj = 0; jj < 64; jj++) {
            float4 v4 = *(float4*)&Vs[jj][tx * 4];
            #pragma unroll
            for (int a = 0; a < 4; a++) {
                float pv = Ps[ty * 4 + a][jj];
                acc[a][0] += pv * v4.x;
                acc[a][1] += pv * v4.y;
                acc[a][2] += pv * v4.z;
                acc[a][3] += pv * v4.w;
            }
        }
        __syncthreads();
    }

    int b = z >> 2, h = z & 3;
    #pragma unroll
    for (int a = 0; a < 4; a++)
        #pragma unroll
        for (int bb = 0; bb < 4; bb++)
            out[((b << 10) + l0 + ty * 4 + a) * 256 + (h << 6) + tx * 4 + bb] = acc[a][bb];
}

// ---------------------------------------------------------------------------
// Final fc stage 1: partial[b][blk][n] = sum over 1024-chunk of flat[b]·W[:,n]
// W row-major (262144, 240). grid 256, block 256.
// ---------------------------------------------------------------------------
__global__ __launch_bounds__(256) void k_fc1(const float* __restrict__ x,
                                             const float* __restrict__ W,
                                             float* __restrict__ part) {
    __shared__ float f0[1024];
    __shared__ float f1[1024];
    int k0 = blockIdx.x * 1024;
    int t = threadIdx.x;
    #pragma unroll
    for (int ff = 0; ff < 4; ff++) {
        int idx = t + ff * 256;
        f0[idx] = x[k0 + idx];
        f1[idx] = x[262144 + k0 + idx];
    }
    __syncthreads();
    if (t < 240) {
        float a0 = 0.f, a1 = 0.f;
        #pragma unroll 8
        for (int kk = 0; kk < 1024; kk++) {
            float w = W[(size_t)(k0 + kk) * 240 + t];
            a0 += f0[kk] * w;
            a1 += f1[kk] * w;
        }
        part[blockIdx.x * 240 + t]         = a0;
        part[61440 + blockIdx.x * 240 + t] = a1;
    }
}

// ---------------------------------------------------------------------------
// Final fc stage 2: reduce 256 partials, add bias, softmax over 240.
// grid 2, block 256.
// ---------------------------------------------------------------------------
__global__ __launch_bounds__(256) void k_fc2(const float* __restrict__ part,
                                             const float* __restrict__ bias,
                                             float* __restrict__ out) {
    int b = blockIdx.x, t = threadIdx.x;
    __shared__ float sm[256];
    float logit = -1e30f;
    if (t < 240) {
        float s = 0.f;
        for (int c = 0; c < 256; c++) s += part[b * 61440 + c * 240 + t];
        logit = s + bias[t];
    }
    sm[t] = logit;
    __syncthreads();
    for (int o = 128; o; o >>= 1) {
        if (t < o) sm[t] = fmaxf(sm[t], sm[t + o]);
        __syncthreads();
    }
    float mx = sm[0];
    __syncthreads();
    float e = (t < 240) ? expf(logit - mx) : 0.f;
    sm[t] = e;
    __syncthreads();
    for (int o = 128; o; o >>= 1) {
        if (t < o) sm[t] += sm[t + o];
        __syncthreads();
    }
    float tot = sm[0];
    if (t < 240) out[b * 240 + t] = e / tot;
}

// ---------------------------------------------------------------------------
// Orchestration
// ---------------------------------------------------------------------------
extern "C" void kernel_launch(void* const* d_in, const int* in_sizes, int n_in,
                              void* d_out, int out_size) {
    const int*   tokens = (const int*)  d_in[0];
    const float* emb    = (const float*)d_in[1];
    const float* pos    = (const float*)d_in[2];
    const float* Wq     = (const float*)d_in[3];
    const float* bq     = (const float*)d_in[4];
    const float* Wk     = (const float*)d_in[5];
    const float* bk     = (const float*)d_in[6];
    const float* Wv     = (const float*)d_in[7];
    const float* bv     = (const float*)d_in[8];
    const float* Wo     = (const float*)d_in[9];
    const float* bo     = (const float*)d_in[10];
    const float* E      = (const float*)d_in[11];
    const float* W1     = (const float*)d_in[12];
    const float* b1     = (const float*)d_in[13];
    const float* W2     = (const float*)d_in[14];
    const float* b2     = (const float*)d_in[15];
    const float* fcW    = (const float*)d_in[16];
    const float* fcb    = (const float*)d_in[17];
    float* out = (float*)d_out;

    float* base = nullptr;
    cudaGetSymbolAddress((void**)&base, g_scratch);
    float* x0   = base + OFF_X0;
    float* x1   = base + OFF_X1;
    float* x2   = base + OFF_X2;
    float* q_   = base + OFF_Q;
    float* k_   = base + OFF_K;
    float* v_   = base + OFF_V;
    float* att  = base + OFF_ATT;
    float* Sb   = base + OFF_S;
    float* QEb  = base + OFF_QE;
    float* part = base + OFF_PART;

    k_embed<<<2048, 256>>>(tokens, emb, pos, x0);

    dim3 gG(4, 32);
    dim3 gS(16, 16, 8);
    dim3 gSm(1024, 8);
    dim3 gA(16, 8);

    float* xin = x0;
    for (int l = 0; l < 6; l++) {
        for (int r = 0; r < 2; r++) {
            int p = l * 2 + r;
            float* xout = (r == 0) ? x1 : x2;
            k_gemm256<<<gG, 256>>>(xin, Wq + p * 65536, bq + p * 256, nullptr, q_, 1);
            k_gemm256<<<gG, 256>>>(xin, Wk + p * 65536, bk + p * 256, nullptr, k_, 1);
            k_gemm256<<<gG, 256>>>(xin, Wv + p * 65536, bv + p * 256, nullptr, v_, 1);
            k_scores<<<gS, 256>>>(q_, k_, Sb, 1);
            k_scores<<<gS, 256>>>(q_, E + p * 65536, QEb, 0);
            k_softmax<<<gSm, 256>>>(Sb, QEb);
            k_av<<<gA, 256>>>(Sb, v_, att);
            k_gemm256<<<gG, 256>>>(att, Wo + p * 65536, bo + p * 256, xin, xout, 2);
            xin = xout;
        }
        k_gemm256<<<gG, 256>>>(xin, W1 + l * 65536, b1 + l * 256, nullptr, att, 4);
        k_gemm256<<<gG, 256>>>(att, W2 + l * 65536, b2 + l * 256, nullptr, x0, 0);
        xin = x0;
    }

    k_fc1<<<256, 256>>>(xin, fcW, part);
    k_fc2<<<2, 256>>>(part, fcb, out);
}

// round 2
// speedup vs baseline: 2.0138x; 2.0138x over previous
#include <cuda_runtime.h>
#include <cstddef>

// ---------------------------------------------------------------------------
// MusicTransformer: B=2, L=1024, D=256, H=4, dh=64, NUM_LAYER=6, V=240
// tf32 tensor-core implementation (mma.sync.m16n8k8).
//
// Skew identity: Srel[i,j] = (j <= i) ? dot(q_i, E[1023 - i + j]) : 0
// fused into the scores kernel tile-locally (127 E rows per 64x64 tile).
// ---------------------------------------------------------------------------

#define XSZ (2*1024*256)               // 524288
#define OFF_X0   0
#define OFF_X1   (OFF_X0 + XSZ)
#define OFF_X2   (OFF_X1 + XSZ)
#define OFF_Q    (OFF_X2 + XSZ)
#define OFF_K    (OFF_Q + XSZ)
#define OFF_V    (OFF_K + XSZ)
#define OFF_ATT  (OFF_V + XSZ)
#define OFF_S    (OFF_ATT + XSZ)                 // 8*1024*1024 logits/probs
#define OFF_PART (OFF_S + 8*1024*1024)           // 2*256*240 fc partials
#define SCRATCH_TOTAL (OFF_PART + 2*256*240)

__device__ float g_scratch[SCRATCH_TOTAL];

// ---------------------------------------------------------------------------
// tf32 mma helpers
// ---------------------------------------------------------------------------
__device__ __forceinline__ unsigned f2tf(float x) {
    unsigned u; asm("cvt.rna.tf32.f32 %0, %1;" : "=r"(u) : "f"(x)); return u;
}
__device__ __forceinline__ void mma8(float* c, const unsigned* a, const unsigned* b) {
    asm volatile("mma.sync.aligned.m16n8k8.row.col.f32.tf32.tf32.f32 "
                 "{%0,%1,%2,%3},{%4,%5,%6,%7},{%8,%9},{%0,%1,%2,%3};"
                 : "+f"(c[0]), "+f"(c[1]), "+f"(c[2]), "+f"(c[3])
                 : "r"(a[0]), "r"(a[1]), "r"(a[2]), "r"(a[3]),
                   "r"(b[0]), "r"(b[1]));
}

// ---------------------------------------------------------------------------
// Embedding
// ---------------------------------------------------------------------------
__global__ __launch_bounds__(256) void k_embed(const int* __restrict__ tokens,
                                               const float* __restrict__ emb,
                                               const float* __restrict__ pos,
                                               float* __restrict__ x) {
    int idx = blockIdx.x * 256 + threadIdx.x;
    int tok = tokens[idx >> 8];
    int d   = idx & 255;
    int pd  = idx & (262144 - 1);
    x[idx] = emb[tok * 256 + d] + pos[pd];
}

// ---------------------------------------------------------------------------
// TC GEMM: out = act(A[2048x256] @ W[256x256] + bias) (+residual)
// 128 threads (4 warps, 2x2), block tile 64x64, BK=32.
// grid (4, 32, nz); z selects W/bias/out (fused QKV).
// flags: 1 split-head output, 2 residual add, 4 leaky relu
// ---------------------------------------------------------------------------
__global__ __launch_bounds__(128) void k_gemm_tc(const float* __restrict__ A,
                                                 const float* __restrict__ W0,
                                                 const float* __restrict__ W1,
                                                 const float* __restrict__ W2,
                                                 const float* __restrict__ bi0,
                                                 const float* __restrict__ bi1,
                                                 const float* __restrict__ bi2,
                                                 float* o0, float* o1, float* o2,
                                                 const float* __restrict__ res,
                                                 int flags) {
    __shared__ float As[64][36];
    __shared__ float Bs[32][68];
    int z = blockIdx.z;
    const float* W    = (z == 0) ? W0  : (z == 1) ? W1  : W2;
    const float* bias = (z == 0) ? bi0 : (z == 1) ? bi1 : bi2;
    float*       out  = (z == 0) ? o0  : (z == 1) ? o1  : o2;

    int t = threadIdx.x, lane = t & 31, warp = t >> 5;
    int g = lane >> 2, tq = lane & 3;
    int wm = (warp >> 1) * 32, wn = (warp & 1) * 32;
    int m0 = blockIdx.y * 64, n0 = blockIdx.x * 64;
    float acc[2][4][4] = {};

    for (int k0 = 0; k0 < 256; k0 += 32) {
        #pragma unroll
        for (int i = 0; i < 4; i++) {
            int idx = t + i * 128;                  // 0..511
            int ra = idx >> 3, ca = (idx & 7) << 2;
            *(float4*)&As[ra][ca] = *(const float4*)&A[(m0 + ra) * 256 + k0 + ca];
            int rw = idx >> 4, cw = (idx & 15) << 2;
            *(float4*)&Bs[rw][cw] = *(const float4*)&W[(k0 + rw) * 256 + n0 + cw];
        }
        __syncthreads();
        #pragma unroll
        for (int ks = 0; ks < 32; ks += 8) {
            unsigned af[2][4], bf[4][2];
            #pragma unroll
            for (int mf = 0; mf < 2; mf++) {
                int r = wm + mf * 16 + g;
                af[mf][0] = f2tf(As[r][ks + tq]);
                af[mf][1] = f2tf(As[r + 8][ks + tq]);
                af[mf][2] = f2tf(As[r][ks + tq + 4]);
                af[mf][3] = f2tf(As[r + 8][ks + tq + 4]);
            }
            #pragma unroll
            for (int nf = 0; nf < 4; nf++) {
                int c = wn + nf * 8 + g;
                bf[nf][0] = f2tf(Bs[ks + tq][c]);
                bf[nf][1] = f2tf(Bs[ks + tq + 4][c]);
            }
            #pragma unroll
            for (int mf = 0; mf < 2; mf++)
                #pragma unroll
                for (int nf = 0; nf < 4; nf++)
                    mma8(acc[mf][nf], af[mf], bf[nf]);
        }
        __syncthreads();
    }

    #pragma unroll
    for (int mf = 0; mf < 2; mf++)
        #pragma unroll
        for (int nf = 0; nf < 4; nf++)
            #pragma unroll
            for (int e = 0; e < 4; e++) {
                int r = m0 + wm + mf * 16 + g + ((e >> 1) << 3);
                int c = n0 + wn + nf * 8 + 2 * tq + (e & 1);
                float v = acc[mf][nf][e] + bias[c];
                if (flags & 4) v = v > 0.f ? v : 0.2f * v;
                if (flags & 2) v += res[r * 256 + c];
                if (flags & 1) {
                    int b = r >> 10, l = r & 1023, h = c >> 6, d = c & 63;
                    out[(((b << 2) + h) << 16) + (l << 6) + d] = v;
                } else {
                    out[r * 256 + c] = v;
                }
            }
}

// ---------------------------------------------------------------------------
// Scores + fused relative skew:
//   S[z][i][j] = (q_i.k_j + (j<=i ? q_i.E[1023-i+j] : 0)) * 0.125
// 128 threads (4 warps 2x2), tile 64x64, dh=64.
// Dynamic smem: Qs[64][68] + Ks[64][68] + Gs[64][68] = 52224 B.
// grid (16 jt, 16 it, 8 z).
// ---------------------------------------------------------------------------
extern __shared__ float s_dyn[];
__global__ __launch_bounds__(128) void k_scores_tc(const float* __restrict__ Q,
                                                   const float* __restrict__ K,
                                                   const float* __restrict__ E,
                                                   float* __restrict__ S) {
    float* Qs = s_dyn;                  // [64][68] row-major [i][d]
    float* Ks = s_dyn + 64 * 68;        // [64][68] row-major [j][d] / [er][d]
    float* Gs = s_dyn + 2 * 64 * 68;    // [64][68] G[di][rloc]

    int z = blockIdx.z, jt = blockIdx.x, it = blockIdx.y;
    const float* Qz = Q + z * 65536;
    const float* Kz = K + z * 65536;
    int t = threadIdx.x, lane = t & 31, warp = t >> 5;
    int g = lane >> 2, tq = lane & 3;
    int wm = (warp >> 1) * 32, wn = (warp & 1) * 32;
    int i0 = it * 64, j0 = jt * 64;

    // load Q and K tiles (row-major, coalesced)
    #pragma unroll
    for (int i = 0; i < 8; i++) {
        int idx = t + i * 128;                     // 0..1023
        int row = idx >> 4, c4 = (idx & 15) << 2;
        *(float4*)&Qs[row * 68 + c4] = *(const float4*)&Qz[(i0 + row) * 64 + c4];
        *(float4*)&Ks[row * 68 + c4] = *(const float4*)&Kz[(j0 + row) * 64 + c4];
    }
    __syncthreads();

    float acc[2][4][4] = {};
    // S = Q @ K^T  (A from Qs[i][d], B from Ks[j][d] i.e. n-major/k-minor)
    #pragma unroll
    for (int ks = 0; ks < 64; ks += 8) {
        unsigned af[2][4], bf[4][2];
        #pragma unroll
        for (int mf = 0; mf < 2; mf++) {
            int r = wm + mf * 16 + g;
            af[mf][0] = f2tf(Qs[r * 68 + ks + tq]);
            af[mf][1] = f2tf(Qs[(r + 8) * 68 + ks + tq]);
            af[mf][2] = f2tf(Qs[r * 68 + ks + tq + 4]);
            af[mf][3] = f2tf(Qs[(r + 8) * 68 + ks + tq + 4]);
        }
        #pragma unroll
        for (int nf = 0; nf < 4; nf++) {
            int c = wn + nf * 8 + g;
            bf[nf][0] = f2tf(Ks[c * 68 + ks + tq]);
            bf[nf][1] = f2tf(Ks[c * 68 + ks + tq + 4]);
        }
        #pragma unroll
        for (int mf = 0; mf < 2; mf++)
            #pragma unroll
            for (int nf = 0; nf < 4; nf++)
                mma8(acc[mf][nf], af[mf], bf[nf]);
    }

    // relative-position part: only tiles with jt <= it have any j<=i
    if (jt <= it) {
        int ebase = 960 + j0 - i0;              // >= 0 always
        int hmax = (it == jt) ? 1 : 2;          // it==jt: only r in [0,63]
        for (int h = 0; h < hmax; h++) {
            __syncthreads();                    // everyone done reading Ks
            #pragma unroll
            for (int i = 0; i < 8; i++) {
                int idx = t + i * 128;
                int row = idx >> 4, c4 = (idx & 15) << 2;
                int er = ebase + h * 64 + row;  // provably in [0,1023]
                *(float4*)&Ks[row * 68 + c4] = *(const float4*)&E[er * 64 + c4];
            }
            __syncthreads();
            float accg[2][4][4] = {};
            #pragma unroll
            for (int ks = 0; ks < 64; ks += 8) {
                unsigned af[2][4], bf[4][2];
                #pragma unroll
                for (int mf = 0; mf < 2; mf++) {
                    int r = wm + mf * 16 + g;
                    af[mf][0] = f2tf(Qs[r * 68 + ks + tq]);
                    af[mf][1] = f2tf(Qs[(r + 8) * 68 + ks + tq]);
                    af[mf][2] = f2tf(Qs[r * 68 + ks + tq + 4]);
                    af[mf][3] = f2tf(Qs[(r + 8) * 68 + ks + tq + 4]);
                }
                #pragma unroll
                for (int nf = 0; nf < 4; nf++) {
                    int c = wn + nf * 8 + g;
                    bf[nf][0] = f2tf(Ks[c * 68 + ks + tq]);
                    bf[nf][1] = f2tf(Ks[c * 68 + ks + tq + 4]);
                }
                #pragma unroll
                for (int mf = 0; mf < 2; mf++)
                    #pragma unroll
                    for (int nf = 0; nf < 4; nf++)
                        mma8(accg[mf][nf], af[mf], bf[nf]);
            }
            // stage G half, then gather-add into acc
            #pragma unroll
            for (int mf = 0; mf < 2; mf++)
                #pragma unroll
                for (int nf = 0; nf < 4; nf++)
                    #pragma unroll
                    for (int e = 0; e < 4; e++) {
                        int di = wm + mf * 16 + g + ((e >> 1) << 3);
                        int dn = wn + nf * 8 + 2 * tq + (e & 1);
                        Gs[di * 68 + dn] = accg[mf][nf][e];
                    }
            __syncthreads();
            #pragma unroll
            for (int mf = 0; mf < 2; mf++)
                #pragma unroll
                for (int nf = 0; nf < 4; nf++)
                    #pragma unroll
                    for (int e = 0; e < 4; e++) {
                        int di = wm + mf * 16 + g + ((e >> 1) << 3);
                        int dj = wn + nf * 8 + 2 * tq + (e & 1);
                        int rloc = 63 - di + dj - h * 64;
                        if (rloc >= 0 && rloc < 64)
                            acc[mf][nf][e] += Gs[di * 68 + rloc];
                    }
        }
    }

    float* Sz = S + ((size_t)z << 20);
    #pragma unroll
    for (int mf = 0; mf < 2; mf++)
        #pragma unroll
        for (int nf = 0; nf < 4; nf++)
            #pragma unroll
            for (int e = 0; e < 4; e++) {
                int di = wm + mf * 16 + g + ((e >> 1) << 3);
                int dj = wn + nf * 8 + 2 * tq + (e & 1);
                Sz[(size_t)(i0 + di) * 1024 + j0 + dj] = acc[mf][nf][e] * 0.125f;
            }
}

// ---------------------------------------------------------------------------
// In-place row softmax over 1024 (logits already scaled).
// grid (1024, 8), block 256, float4 per thread.
// ---------------------------------------------------------------------------
__global__ __launch_bounds__(256) void k_softmax(float* __restrict__ S) {
    int i = blockIdx.x, z = blockIdx.y, t = threadIdx.x;
    float* row = S + ((size_t)z << 20) + ((size_t)i << 10);
    float4 v = *(float4*)&row[t * 4];
    float mx = fmaxf(fmaxf(v.x, v.y), fmaxf(v.z, v.w));

    __shared__ float red[8];
    int lane = t & 31, warp = t >> 5;
    #pragma unroll
    for (int o = 16; o; o >>= 1) mx = fmaxf(mx, __shfl_xor_sync(~0u, mx, o));
    if (lane == 0) red[warp] = mx;
    __syncthreads();
    if (t < 8) {
        float m = red[t];
        #pragma unroll
        for (int o = 4; o; o >>= 1) m = fmaxf(m, __shfl_xor_sync(0xffu, m, o));
        red[t] = m;
    }
    __syncthreads();
    mx = red[0];

    v.x = expf(v.x - mx); v.y = expf(v.y - mx);
    v.z = expf(v.z - mx); v.w = expf(v.w - mx);
    float s = v.x + v.y + v.z + v.w;
    #pragma unroll
    for (int o = 16; o; o >>= 1) s += __shfl_xor_sync(~0u, s, o);
    __shared__ float red2[8];
    if (lane == 0) red2[warp] = s;
    __syncthreads();
    if (t < 8) {
        float m = red2[t];
        #pragma unroll
        for (int o = 4; o; o >>= 1) m += __shfl_xor_sync(0xffu, m, o);
        red2[t] = m;
    }
    __syncthreads();
    float inv = 1.f / red2[0];
    v.x *= inv; v.y *= inv; v.z *= inv; v.w *= inv;
    *(float4*)&row[t * 4] = v;
}

// ---------------------------------------------------------------------------
// AV: out[b, l, h*64+d] = sum_j P[z][l][j] * V[z][j][d]
// 128 threads, tile 64x64 (full dh), BK=32, grid (16, 8).
// ---------------------------------------------------------------------------
__global__ __launch_bounds__(128) void k_av_tc(const float* __restrict__ P,
                                               const float* __restrict__ Vm,
                                               float* __restrict__ out) {
    __shared__ float Ps[64][36];
    __shared__ float Vs[32][68];
    int z = blockIdx.y;
    const float* Pz = P + ((size_t)z << 20);
    const float* Vz = Vm + z * 65536;
    int t = threadIdx.x, lane = t & 31, warp = t >> 5;
    int g = lane >> 2, tq = lane & 3;
    int wm = (warp >> 1) * 32, wn = (warp & 1) * 32;
    int l0 = blockIdx.x * 64;
    float acc[2][4][4] = {};

    for (int k0 = 0; k0 < 1024; k0 += 32) {
        #pragma unroll
        for (int i = 0; i < 4; i++) {
            int idx = t + i * 128;
            int rp = idx >> 3, cp = (idx & 7) << 2;
            *(float4*)&Ps[rp][cp] = *(const float4*)&Pz[(size_t)(l0 + rp) * 1024 + k0 + cp];
            int rv = idx >> 4, cv = (idx & 15) << 2;
            *(float4*)&Vs[rv][cv] = *(const float4*)&Vz[(k0 + rv) * 64 + cv];
        }
        __syncthreads();
        #pragma unroll
        for (int ks = 0; ks < 32; ks += 8) {
            unsigned af[2][4], bf[4][2];
            #pragma unroll
            for (int mf = 0; mf < 2; mf++) {
                int r = wm + mf * 16 + g;
                af[mf][0] = f2tf(Ps[r][ks + tq]);
                af[mf][1] = f2tf(Ps[r + 8][ks + tq]);
                af[mf][2] = f2tf(Ps[r][ks + tq + 4]);
                af[mf][3] = f2tf(Ps[r + 8][ks + tq + 4]);
            }
            #pragma unroll
            for (int nf = 0; nf < 4; nf++) {
                int c = wn + nf * 8 + g;
                bf[nf][0] = f2tf(Vs[ks + tq][c]);
                bf[nf][1] = f2tf(Vs[ks + tq + 4][c]);
            }
            #pragma unroll
            for (int mf = 0; mf < 2; mf++)
                #pragma unroll
                for (int nf = 0; nf < 4; nf++)
                    mma8(acc[mf][nf], af[mf], bf[nf]);
        }
        __syncthreads();
    }

    int b = z >> 2, h = z & 3;
    #pragma unroll
    for (int mf = 0; mf < 2; mf++)
        #pragma unroll
        for (int nf = 0; nf < 4; nf++)
            #pragma unroll
            for (int e = 0; e < 4; e++) {
                int r = l0 + wm + mf * 16 + g + ((e >> 1) << 3);
                int c = wn + nf * 8 + 2 * tq + (e & 1);
                out[((b << 10) + r) * 256 + (h << 6) + c] = acc[mf][nf][e];
            }
}

// ---------------------------------------------------------------------------
// Final fc stage 1 (memory-bound, SIMT fp32)
// ---------------------------------------------------------------------------
__global__ __launch_bounds__(256) void k_fc1(const float* __restrict__ x,
                                             const float* __restrict__ W,
                                             float* __restrict__ part) {
    __shared__ float f0[1024];
    __shared__ float f1[1024];
    int k0 = blockIdx.x * 1024;
    int t = threadIdx.x;
    #pragma unroll
    for (int ff = 0; ff < 4; ff++) {
        int idx = t + ff * 256;
        f0[idx] = x[k0 + idx];
        f1[idx] = x[262144 + k0 + idx];
    }
    __syncthreads();
    if (t < 240) {
        float a0 = 0.f, a1 = 0.f;
        #pragma unroll 8
        for (int kk = 0; kk < 1024; kk++) {
            float w = W[(size_t)(k0 + kk) * 240 + t];
            a0 += f0[kk] * w;
            a1 += f1[kk] * w;
        }
        part[blockIdx.x * 240 + t]         = a0;
        part[61440 + blockIdx.x * 240 + t] = a1;
    }
}

__global__ __launch_bounds__(256) void k_fc2(const float* __restrict__ part,
                                             const float* __restrict__ bias,
                                             float* __restrict__ out) {
    int b = blockIdx.x, t = threadIdx.x;
    __shared__ float sm[256];
    float logit = -1e30f;
    if (t < 240) {
        float s = 0.f;
        for (int c = 0; c < 256; c++) s += part[b * 61440 + c * 240 + t];
        logit = s + bias[t];
    }
    sm[t] = logit;
    __syncthreads();
    for (int o = 128; o; o >>= 1) {
        if (t < o) sm[t] = fmaxf(sm[t], sm[t + o]);
        __syncthreads();
    }
    float mx = sm[0];
    __syncthreads();
    float e = (t < 240) ? expf(logit - mx) : 0.f;
    sm[t] = e;
    __syncthreads();
    for (int o = 128; o; o >>= 1) {
        if (t < o) sm[t] += sm[t + o];
        __syncthreads();
    }
    float tot = sm[0];
    if (t < 240) out[b * 240 + t] = e / tot;
}

// ---------------------------------------------------------------------------
// Orchestration
// ---------------------------------------------------------------------------
extern "C" void kernel_launch(void* const* d_in, const int* in_sizes, int n_in,
                              void* d_out, int out_size) {
    const int*   tokens = (const int*)  d_in[0];
    const float* emb    = (const float*)d_in[1];
    const float* pos    = (const float*)d_in[2];
    const float* Wq     = (const float*)d_in[3];
    const float* bq     = (const float*)d_in[4];
    const float* Wk     = (const float*)d_in[5];
    const float* bk     = (const float*)d_in[6];
    const float* Wv     = (const float*)d_in[7];
    const float* bv     = (const float*)d_in[8];
    const float* Wo     = (const float*)d_in[9];
    const float* bo     = (const float*)d_in[10];
    const float* E      = (const float*)d_in[11];
    const float* W1     = (const float*)d_in[12];
    const float* b1     = (const float*)d_in[13];
    const float* W2     = (const float*)d_in[14];
    const float* b2     = (const float*)d_in[15];
    const float* fcW    = (const float*)d_in[16];
    const float* fcb    = (const float*)d_in[17];
    float* out = (float*)d_out;

    float* base = nullptr;
    cudaGetSymbolAddress((void**)&base, g_scratch);
    float* x0   = base + OFF_X0;
    float* x1   = base + OFF_X1;
    float* x2   = base + OFF_X2;
    float* q_   = base + OFF_Q;
    float* k_   = base + OFF_K;
    float* v_   = base + OFF_V;
    float* att  = base + OFF_ATT;
    float* Sb   = base + OFF_S;
    float* part = base + OFF_PART;

    const int SCORES_SMEM = 3 * 64 * 68 * 4;     // 52224 B
    cudaFuncSetAttribute(k_scores_tc,
                         cudaFuncAttributeMaxDynamicSharedMemorySize, SCORES_SMEM);

    k_embed<<<2048, 256>>>(tokens, emb, pos, x0);

    dim3 gQKV(4, 32, 3);
    dim3 gG(4, 32, 1);
    dim3 gS(16, 16, 8);
    dim3 gSm(1024, 8);
    dim3 gA(16, 8);

    float* xin = x0;
    for (int l = 0; l < 6; l++) {
        for (int r = 0; r < 2; r++) {
            int p = l * 2 + r;
            float* xout = (r == 0) ? x1 : x2;
            k_gemm_tc<<<gQKV, 128>>>(xin,
                Wq + p * 65536, Wk + p * 65536, Wv + p * 65536,
                bq + p * 256,   bk + p * 256,   bv + p * 256,
                q_, k_, v_, nullptr, 1);
            k_scores_tc<<<gS, 128, SCORES_SMEM>>>(q_, k_, E + p * 65536, Sb);
            k_softmax<<<gSm, 256>>>(Sb);
            k_av_tc<<<gA, 128>>>(Sb, v_, att);
            k_gemm_tc<<<gG, 128>>>(att,
                Wo + p * 65536, Wo + p * 65536, Wo + p * 65536,
                bo + p * 256,   bo + p * 256,   bo + p * 256,
                xout, xout, xout, xin, 2);
            xin = xout;
        }
        k_gemm_tc<<<gG, 128>>>(xin, W1 + l * 65536, W1 + l * 65536, W1 + l * 65536,
                               b1 + l * 256, b1 + l * 256, b1 + l * 256,
                               att, att, att, nullptr, 4);
        k_gemm_tc<<<gG, 128>>>(att, W2 + l * 65536, W2 + l * 65536, W2 + l * 65536,
                               b2 + l * 256, b2 + l * 256, b2 + l * 256,
                               x0, x0, x0, nullptr, 0);
        xin = x0;
    }

    k_fc1<<<256, 256>>>(xin, fcW, part);
    k_fc2<<<2, 256>>>(part, fcb, out);
}